// round 5
// baseline (speedup 1.0000x reference)
#include <cuda_runtime.h>
#include <math.h>
#include <stdint.h>

// Problem constants (fixed by setup_inputs)
#define NI     16
#define TQ     1369
#define TS     5476
#define DD     768
#define MT     11          // ceil(TQ/128) m-tiles
#define SPLIT  4           // s split chunks
#define SCHUNK 1369        // TS / SPLIT
#define STILES 22          // ceil(SCHUNK/64)
#define BM     128
#define BN     64
#define BK     16
#define KK     8           // BK/2 k-pairs
#define NCH    48          // DD/BK chunks

typedef unsigned long long u64;

__device__ __forceinline__ void fma2(u64& d, u64 a, u64 b) {
    asm("fma.rn.f32x2 %0, %1, %2, %0;" : "+l"(d) : "l"(a), "l"(b));
}
__device__ __forceinline__ void unpack2(u64 v, float& lo, float& hi) {
    asm("mov.b64 {%0,%1}, %2;" : "=f"(lo), "=f"(hi) : "l"(v));
}

// ---- scratch (device globals; no runtime allocation) ----
__device__ float g_rq  [NI*TQ];
__device__ float g_qw1 [NI*TQ];
__device__ float g_rs  [NI*TS];
__device__ float g_sw2 [NI*TS];
__device__ float g_clsc[NI];
__device__ float g_pmax[NI*MT*SPLIT*BM];
__device__ int   g_pidx[NI*MT*SPLIT*BM];

// ============================================================
// Pass 1: per-row inverse norms + head partial dots (one pass)
//   rq[n,t]   = 1/max(||q||,eps)      qw1[n,t] = (q.w1)*rq
//   rs[n,s]   = 1/max(||s||,eps)      sw2[n,s] = (s.w2)*rs
//   clsc[n]   = (mean_cls . w3)/max(||mean_cls||,eps) + b
// ============================================================
__global__ void prep_kernel(const float* __restrict__ xq,
                            const float* __restrict__ xs,
                            const float* __restrict__ xc,
                            const float* __restrict__ W,
                            const float* __restrict__ b)
{
    const int gw   = (blockIdx.x * blockDim.x + threadIdx.x) >> 5;
    const int lane = threadIdx.x & 31;
    const int NQ = NI*TQ, NS = NI*TS;

    float ss = 0.f, dw = 0.f;
    if (gw < NQ) {
        const float* x = xq + (size_t)gw * DD;
        for (int j = lane; j < DD; j += 32) { float v = x[j]; ss += v*v; dw += v*W[j]; }
        #pragma unroll
        for (int o = 16; o; o >>= 1) { ss += __shfl_xor_sync(~0u, ss, o); dw += __shfl_xor_sync(~0u, dw, o); }
        if (!lane) { float rn = 1.f / fmaxf(sqrtf(ss), 1e-12f); g_rq[gw] = rn; g_qw1[gw] = dw * rn; }
    } else if (gw < NQ + NS) {
        const int r = gw - NQ;
        const float* x = xs + (size_t)r * DD;
        for (int j = lane; j < DD; j += 32) { float v = x[j]; ss += v*v; dw += v*W[DD + j]; }
        #pragma unroll
        for (int o = 16; o; o >>= 1) { ss += __shfl_xor_sync(~0u, ss, o); dw += __shfl_xor_sync(~0u, dw, o); }
        if (!lane) { float rn = 1.f / fmaxf(sqrtf(ss), 1e-12f); g_rs[r] = rn; g_sw2[r] = dw * rn; }
    } else if (gw < NQ + NS + NI) {
        const int n = gw - NQ - NS;
        const float* x = xc + (size_t)n * 4 * DD;
        for (int j = lane; j < DD; j += 32) {
            float m = 0.25f * (x[j] + x[DD + j] + x[2*DD + j] + x[3*DD + j]);
            ss += m*m; dw += m * W[2*DD + j];
        }
        #pragma unroll
        for (int o = 16; o; o >>= 1) { ss += __shfl_xor_sync(~0u, ss, o); dw += __shfl_xor_sync(~0u, dw, o); }
        if (!lane) g_clsc[n] = dw / fmaxf(sqrtf(ss), 1e-12f) + b[0];
    }
}

// ============================================================
// Pass 2: fused raw-GEMM + running (max, argmax) per query row
// grid (SPLIT, MT, NI), 256 threads, BM=128 x BN=64 tile,
// 8x4 thread tile, f32x2 paired along K (even/odd partial sums)
// ============================================================
__global__ void __launch_bounds__(256, 2) main_kernel(
    const float* __restrict__ xq, const float* __restrict__ xs)
{
    const int t  = threadIdx.x;
    const int tx = t & 15, ty = t >> 4;
    const int n  = blockIdx.z, mt = blockIdx.y, sc = blockIdx.x;
    const int m0 = mt * BM;
    const int cb  = tx * 4;   // 4 columns per thread
    const int tm0 = ty * 8;   // 8 rows per thread

    const float* qb = xq + (size_t)n * TQ * DD;
    const float* sb = xs + ((size_t)n * TS + (size_t)sc * SCHUNK) * DD;

    __shared__ __align__(16) float2 As2[2][KK][BM + 2];  // [kpair][row] = (k_even,k_odd)
    __shared__ __align__(16) float2 Bs2[2][KK][BN + 2];  // [kpair][col]
    __shared__ float rss[BN];

    const int lr = t >> 2;         // 0..63  (row within load slab)
    const int lk = (t & 3) * 4;    // 0,4,8,12 (k offset, float4)
    const int kp = lk >> 1;        // k-pair index 0,2,4,6

    float vmax[8]; int vidx[8];
    #pragma unroll
    for (int i = 0; i < 8; i++) { vmax[i] = -1e30f; vidx[i] = 0; }

    const bool okA0 = (m0 + lr)      < TQ;
    const bool okA1 = (m0 + lr + 64) < TQ;
    const float4 z4 = make_float4(0.f, 0.f, 0.f, 0.f);

    #pragma unroll 1
    for (int st = 0; st < STILES; st++) {
        __syncthreads();  // protect rss + smem buffers across s-tiles
        if (t < BN) {
            int loc = st * BN + t;
            rss[t] = (loc < SCHUNK) ? g_rs[(size_t)n * TS + sc * SCHUNK + loc]
                                    : __int_as_float(0x7FC00000); // NaN: never wins max
        }
        const bool okB = (st * BN + lr) < SCHUNK;
        const float* arow0 = qb + (size_t)(m0 + lr) * DD + lk;
        const float* arow1 = arow0 + (size_t)64 * DD;
        const float* brow  = sb + (size_t)(st * BN + lr) * DD + lk;

        // prefetch chunk 0
        float4 va0 = okA0 ? *(const float4*)(arow0) : z4;
        float4 va1 = okA1 ? *(const float4*)(arow1) : z4;
        float4 vb  = okB  ? *(const float4*)(brow)  : z4;

        u64 acc[8][4];
        #pragma unroll
        for (int i = 0; i < 8; i++)
            #pragma unroll
            for (int j = 0; j < 4; j++) acc[i][j] = 0ull;

        #pragma unroll 1
        for (int c = 0; c < NCH; c++) {
            const int bf = c & 1;
            As2[bf][kp    ][lr     ] = make_float2(va0.x, va0.y);
            As2[bf][kp + 1][lr     ] = make_float2(va0.z, va0.w);
            As2[bf][kp    ][lr + 64] = make_float2(va1.x, va1.y);
            As2[bf][kp + 1][lr + 64] = make_float2(va1.z, va1.w);
            Bs2[bf][kp    ][lr     ] = make_float2(vb.x, vb.y);
            Bs2[bf][kp + 1][lr     ] = make_float2(vb.z, vb.w);
            if (c + 1 < NCH) {            // prefetch next chunk (latency overlapped)
                int ko = (c + 1) * BK;
                va0 = okA0 ? *(const float4*)(arow0 + ko) : z4;
                va1 = okA1 ? *(const float4*)(arow1 + ko) : z4;
                vb  = okB  ? *(const float4*)(brow  + ko) : z4;
            }
            __syncthreads();              // single barrier per chunk (2-buffer)

            #pragma unroll
            for (int k2 = 0; k2 < KK; k2++) {
                ulonglong2 a01 = *(const ulonglong2*)&As2[bf][k2][tm0];
                ulonglong2 a23 = *(const ulonglong2*)&As2[bf][k2][tm0 + 2];
                ulonglong2 a45 = *(const ulonglong2*)&As2[bf][k2][tm0 + 4];
                ulonglong2 a67 = *(const ulonglong2*)&As2[bf][k2][tm0 + 6];
                ulonglong2 b01 = *(const ulonglong2*)&Bs2[bf][k2][cb];
                ulonglong2 b23 = *(const ulonglong2*)&Bs2[bf][k2][cb + 2];
                u64 a[8] = {a01.x, a01.y, a23.x, a23.y, a45.x, a45.y, a67.x, a67.y};
                u64 b[4] = {b01.x, b01.y, b23.x, b23.y};
                #pragma unroll
                for (int i = 0; i < 8; i++)
                    #pragma unroll
                    for (int j = 0; j < 4; j++)
                        fma2(acc[i][j], a[i], b[j]);
            }
        }

        // epilogue: fold tile into running per-row (max, argmax)
        #pragma unroll
        for (int i = 0; i < 8; i++) {
            #pragma unroll
            for (int j = 0; j < 4; j++) {
                float lo, hi; unpack2(acc[i][j], lo, hi);
                float sim = (lo + hi) * rss[cb + j];   // NaN for OOB cols -> rejected
                if (sim > vmax[i]) { vmax[i] = sim; vidx[i] = st * BN + cb + j; }
            }
        }
    }

    // reduce across the 16 threads sharing each row (tie -> smaller idx)
    #pragma unroll
    for (int i = 0; i < 8; i++) {
        float v = vmax[i]; int id = vidx[i];
        #pragma unroll
        for (int o = 8; o; o >>= 1) {
            float ov = __shfl_down_sync(0xFFFFFFFFu, v,  o, 16);
            int   oi = __shfl_down_sync(0xFFFFFFFFu, id, o, 16);
            if (ov > v || (ov == v && oi < id)) { v = ov; id = oi; }
        }
        if (tx == 0) {
            int p = ((n * MT + mt) * SPLIT + sc) * BM + tm0 + i;
            g_pmax[p] = v;
            g_pidx[p] = sc * SCHUNK + id;   // global s index within batch n
        }
    }
}

// ============================================================
// Pass 3: combine s-chunks, apply head, write both outputs
// ============================================================
__global__ void final_kernel(float* __restrict__ out)
{
    int r = blockIdx.x * blockDim.x + threadIdx.x;
    if (r >= NI * TQ) return;
    int n = r / TQ, m = r % TQ;
    int mt = m >> 7, ml = m & 127;
    int base = ((n * MT + mt) * SPLIT) * BM + ml;

    float best = -1e30f; int bid = 0;
    #pragma unroll
    for (int sc = 0; sc < SPLIT; sc++) {
        float v = g_pmax[base + sc * BM];
        int  id = g_pidx[base + sc * BM];
        if (v > best || (v == best && id < bid)) { best = v; bid = id; }
    }
    float sim  = best * g_rq[r];
    float dmin = 1.f - sim;
    float lg   = g_qw1[r] + g_sw2[(size_t)n * TS + bid] + g_clsc[n];
    float pred = 1.f / (1.f + expf(-lg));
    out[r]           = pred * dmin;   // output 0: pred*dmin, [N,1,37,37] flat
    out[NI * TQ + r] = pred;          // output 1: pred
}

// ============================================================
extern "C" void kernel_launch(void* const* d_in, const int* in_sizes, int n_in,
                              void* d_out, int out_size)
{
    const float* xq = (const float*)d_in[0];  // [16,1369,768]
    const float* xs = (const float*)d_in[1];  // [16,5476,768]
    const float* xc = (const float*)d_in[2];  // [16,4,768]
    const float* W  = (const float*)d_in[3];  // [2304,1]
    const float* b  = (const float*)d_in[4];  // [1]
    float* out = (float*)d_out;

    const int rows = NI*TQ + NI*TS + NI;               // one warp per row
    const int pblocks = (rows * 32 + 255) / 256;
    prep_kernel<<<pblocks, 256>>>(xq, xs, xc, W, b);

    dim3 grid(SPLIT, MT, NI);                          // n slowest -> L2 locality
    main_kernel<<<grid, 256>>>(xq, xs);

    final_kernel<<<(NI*TQ + 255) / 256, 256>>>(out);
}

// round 6
// speedup vs baseline: 1.0012x; 1.0012x over previous
#include <cuda_runtime.h>
#include <math.h>
#include <stdint.h>

// Problem constants (fixed by setup_inputs)
#define NI     16
#define TQ     1369
#define TS     5476
#define DD     768
#define MT     11          // ceil(TQ/128) m-tiles
#define SPLIT  4           // s split chunks
#define SCHUNK 1369        // TS / SPLIT
#define STILES 22          // ceil(SCHUNK/64)
#define BM     128
#define BN     64
#define BK     16
#define KK     8           // BK/2 k-pairs
#define NCH    48          // DD/BK chunks

typedef unsigned long long u64;

__device__ __forceinline__ void fma2(u64& d, u64 a, u64 b) {
    asm("fma.rn.f32x2 %0, %1, %2, %0;" : "+l"(d) : "l"(a), "l"(b));
}
__device__ __forceinline__ void unpack2(u64 v, float& lo, float& hi) {
    asm("mov.b64 {%0,%1}, %2;" : "=f"(lo), "=f"(hi) : "l"(v));
}

// ---- scratch (device globals; no runtime allocation) ----
__device__ float g_rq  [NI*TQ];
__device__ float g_qw1 [NI*TQ];
__device__ float g_rs  [NI*TS];
__device__ float g_sw2 [NI*TS];
__device__ float g_clsc[NI];
__device__ float g_pmax[NI*MT*SPLIT*BM];
__device__ int   g_pidx[NI*MT*SPLIT*BM];

// ============================================================
// Pass 1: per-row inverse norms + head partial dots (one pass)
//   rq[n,t]   = 1/max(||q||,eps)      qw1[n,t] = (q.w1)*rq
//   rs[n,s]   = 1/max(||s||,eps)      sw2[n,s] = (s.w2)*rs
//   clsc[n]   = (mean_cls . w3)/max(||mean_cls||,eps) + b
// ============================================================
__global__ void prep_kernel(const float* __restrict__ xq,
                            const float* __restrict__ xs,
                            const float* __restrict__ xc,
                            const float* __restrict__ W,
                            const float* __restrict__ b)
{
    const int gw   = (blockIdx.x * blockDim.x + threadIdx.x) >> 5;
    const int lane = threadIdx.x & 31;
    const int NQ = NI*TQ, NS = NI*TS;

    float ss = 0.f, dw = 0.f;
    if (gw < NQ) {
        const float* x = xq + (size_t)gw * DD;
        for (int j = lane; j < DD; j += 32) { float v = x[j]; ss += v*v; dw += v*W[j]; }
        #pragma unroll
        for (int o = 16; o; o >>= 1) { ss += __shfl_xor_sync(~0u, ss, o); dw += __shfl_xor_sync(~0u, dw, o); }
        if (!lane) { float rn = 1.f / fmaxf(sqrtf(ss), 1e-12f); g_rq[gw] = rn; g_qw1[gw] = dw * rn; }
    } else if (gw < NQ + NS) {
        const int r = gw - NQ;
        const float* x = xs + (size_t)r * DD;
        for (int j = lane; j < DD; j += 32) { float v = x[j]; ss += v*v; dw += v*W[DD + j]; }
        #pragma unroll
        for (int o = 16; o; o >>= 1) { ss += __shfl_xor_sync(~0u, ss, o); dw += __shfl_xor_sync(~0u, dw, o); }
        if (!lane) { float rn = 1.f / fmaxf(sqrtf(ss), 1e-12f); g_rs[r] = rn; g_sw2[r] = dw * rn; }
    } else if (gw < NQ + NS + NI) {
        const int n = gw - NQ - NS;
        const float* x = xc + (size_t)n * 4 * DD;
        for (int j = lane; j < DD; j += 32) {
            float m = 0.25f * (x[j] + x[DD + j] + x[2*DD + j] + x[3*DD + j]);
            ss += m*m; dw += m * W[2*DD + j];
        }
        #pragma unroll
        for (int o = 16; o; o >>= 1) { ss += __shfl_xor_sync(~0u, ss, o); dw += __shfl_xor_sync(~0u, dw, o); }
        if (!lane) g_clsc[n] = dw / fmaxf(sqrtf(ss), 1e-12f) + b[0];
    }
}

// ============================================================
// Pass 2: fused raw-GEMM + running (max, argmax) per query row
// grid (SPLIT, MT, NI), 256 threads, BM=128 x BN=64 tile,
// 8x4 thread tile, f32x2 paired along K (even/odd partial sums)
// ============================================================
__global__ void __launch_bounds__(256, 2) main_kernel(
    const float* __restrict__ xq, const float* __restrict__ xs)
{
    const int t  = threadIdx.x;
    const int tx = t & 15, ty = t >> 4;
    const int n  = blockIdx.z, mt = blockIdx.y, sc = blockIdx.x;
    const int m0 = mt * BM;
    const int cb  = tx * 4;   // 4 columns per thread
    const int tm0 = ty * 8;   // 8 rows per thread

    const float* qb = xq + (size_t)n * TQ * DD;
    const float* sb = xs + ((size_t)n * TS + (size_t)sc * SCHUNK) * DD;

    __shared__ __align__(16) float2 As2[2][KK][BM + 2];  // [kpair][row] = (k_even,k_odd)
    __shared__ __align__(16) float2 Bs2[2][KK][BN + 2];  // [kpair][col]
    __shared__ float rss[BN];

    const int lr = t >> 2;         // 0..63  (row within load slab)
    const int lk = (t & 3) * 4;    // 0,4,8,12 (k offset, float4)
    const int kp = lk >> 1;        // k-pair index 0,2,4,6

    float vmax[8]; int vidx[8];
    #pragma unroll
    for (int i = 0; i < 8; i++) { vmax[i] = -1e30f; vidx[i] = 0; }

    const bool okA0 = (m0 + lr)      < TQ;
    const bool okA1 = (m0 + lr + 64) < TQ;
    const float4 z4 = make_float4(0.f, 0.f, 0.f, 0.f);

    #pragma unroll 1
    for (int st = 0; st < STILES; st++) {
        __syncthreads();  // protect rss + smem buffers across s-tiles
        if (t < BN) {
            int loc = st * BN + t;
            rss[t] = (loc < SCHUNK) ? g_rs[(size_t)n * TS + sc * SCHUNK + loc]
                                    : __int_as_float(0x7FC00000); // NaN: never wins max
        }
        const bool okB = (st * BN + lr) < SCHUNK;
        const float* arow0 = qb + (size_t)(m0 + lr) * DD + lk;
        const float* arow1 = arow0 + (size_t)64 * DD;
        const float* brow  = sb + (size_t)(st * BN + lr) * DD + lk;

        // prefetch chunk 0
        float4 va0 = okA0 ? *(const float4*)(arow0) : z4;
        float4 va1 = okA1 ? *(const float4*)(arow1) : z4;
        float4 vb  = okB  ? *(const float4*)(brow)  : z4;

        u64 acc[8][4];
        #pragma unroll
        for (int i = 0; i < 8; i++)
            #pragma unroll
            for (int j = 0; j < 4; j++) acc[i][j] = 0ull;

        #pragma unroll 1
        for (int c = 0; c < NCH; c++) {
            const int bf = c & 1;
            As2[bf][kp    ][lr     ] = make_float2(va0.x, va0.y);
            As2[bf][kp + 1][lr     ] = make_float2(va0.z, va0.w);
            As2[bf][kp    ][lr + 64] = make_float2(va1.x, va1.y);
            As2[bf][kp + 1][lr + 64] = make_float2(va1.z, va1.w);
            Bs2[bf][kp    ][lr     ] = make_float2(vb.x, vb.y);
            Bs2[bf][kp + 1][lr     ] = make_float2(vb.z, vb.w);
            if (c + 1 < NCH) {            // prefetch next chunk (latency overlapped)
                int ko = (c + 1) * BK;
                va0 = okA0 ? *(const float4*)(arow0 + ko) : z4;
                va1 = okA1 ? *(const float4*)(arow1 + ko) : z4;
                vb  = okB  ? *(const float4*)(brow  + ko) : z4;
            }
            __syncthreads();              // single barrier per chunk (2-buffer)

            #pragma unroll
            for (int k2 = 0; k2 < KK; k2++) {
                ulonglong2 a01 = *(const ulonglong2*)&As2[bf][k2][tm0];
                ulonglong2 a23 = *(const ulonglong2*)&As2[bf][k2][tm0 + 2];
                ulonglong2 a45 = *(const ulonglong2*)&As2[bf][k2][tm0 + 4];
                ulonglong2 a67 = *(const ulonglong2*)&As2[bf][k2][tm0 + 6];
                ulonglong2 b01 = *(const ulonglong2*)&Bs2[bf][k2][cb];
                ulonglong2 b23 = *(const ulonglong2*)&Bs2[bf][k2][cb + 2];
                u64 a[8] = {a01.x, a01.y, a23.x, a23.y, a45.x, a45.y, a67.x, a67.y};
                u64 b[4] = {b01.x, b01.y, b23.x, b23.y};
                #pragma unroll
                for (int i = 0; i < 8; i++)
                    #pragma unroll
                    for (int j = 0; j < 4; j++)
                        fma2(acc[i][j], a[i], b[j]);
            }
        }

        // epilogue: fold tile into running per-row (max, argmax)
        #pragma unroll
        for (int i = 0; i < 8; i++) {
            #pragma unroll
            for (int j = 0; j < 4; j++) {
                float lo, hi; unpack2(acc[i][j], lo, hi);
                float sim = (lo + hi) * rss[cb + j];   // NaN for OOB cols -> rejected
                if (sim > vmax[i]) { vmax[i] = sim; vidx[i] = st * BN + cb + j; }
            }
        }
    }

    // reduce across the 16 threads sharing each row (tie -> smaller idx)
    #pragma unroll
    for (int i = 0; i < 8; i++) {
        float v = vmax[i]; int id = vidx[i];
        #pragma unroll
        for (int o = 8; o; o >>= 1) {
            float ov = __shfl_down_sync(0xFFFFFFFFu, v,  o, 16);
            int   oi = __shfl_down_sync(0xFFFFFFFFu, id, o, 16);
            if (ov > v || (ov == v && oi < id)) { v = ov; id = oi; }
        }
        if (tx == 0) {
            int p = ((n * MT + mt) * SPLIT + sc) * BM + tm0 + i;
            g_pmax[p] = v;
            g_pidx[p] = sc * SCHUNK + id;   // global s index within batch n
        }
    }
}

// ============================================================
// Pass 3: combine s-chunks, apply head, write both outputs
// ============================================================
__global__ void final_kernel(float* __restrict__ out)
{
    int r = blockIdx.x * blockDim.x + threadIdx.x;
    if (r >= NI * TQ) return;
    int n = r / TQ, m = r % TQ;
    int mt = m >> 7, ml = m & 127;
    int base = ((n * MT + mt) * SPLIT) * BM + ml;

    float best = -1e30f; int bid = 0;
    #pragma unroll
    for (int sc = 0; sc < SPLIT; sc++) {
        float v = g_pmax[base + sc * BM];
        int  id = g_pidx[base + sc * BM];
        if (v > best || (v == best && id < bid)) { best = v; bid = id; }
    }
    float sim  = best * g_rq[r];
    float dmin = 1.f - sim;
    float lg   = g_qw1[r] + g_sw2[(size_t)n * TS + bid] + g_clsc[n];
    float pred = 1.f / (1.f + expf(-lg));
    out[r]           = pred * dmin;   // output 0: pred*dmin, [N,1,37,37] flat
    out[NI * TQ + r] = pred;          // output 1: pred
}

// ============================================================
extern "C" void kernel_launch(void* const* d_in, const int* in_sizes, int n_in,
                              void* d_out, int out_size)
{
    const float* xq = (const float*)d_in[0];  // [16,1369,768]
    const float* xs = (const float*)d_in[1];  // [16,5476,768]
    const float* xc = (const float*)d_in[2];  // [16,4,768]
    const float* W  = (const float*)d_in[3];  // [2304,1]
    const float* b  = (const float*)d_in[4];  // [1]
    float* out = (float*)d_out;

    const int rows = NI*TQ + NI*TS + NI;               // one warp per row
    const int pblocks = (rows * 32 + 255) / 256;
    prep_kernel<<<pblocks, 256>>>(xq, xs, xc, W, b);

    dim3 grid(SPLIT, MT, NI);                          // n slowest -> L2 locality
    main_kernel<<<grid, 256>>>(xq, xs);

    final_kernel<<<(NI*TQ + 255) / 256, 256>>>(out);
}